// round 16
// baseline (speedup 1.0000x reference)
#include <cuda_runtime.h>
#include <cuda_bf16.h>
#include <cuda_fp8.h>
#include <cstdint>
#include <math.h>

#define DEV __device__ __forceinline__

// ---------------------------------------------------------------------------
// Problem constants
// ---------------------------------------------------------------------------
static constexpr int M_TOTAL = 16384;   // B*S
static constexpr int N_TOTAL = 2048;    // OUT
static constexpr int K_TOTAL = 2048;    // IN

static constexpr int BM = 128;
static constexpr int BN = 128;
static constexpr int BK = 128;                   // fp8 bytes per K-chunk (full row)
static constexpr int NUM_CHUNKS = K_TOTAL / BK;  // 16
static constexpr int STAGES = 3;
static constexpr int RS = 144;                   // padded row stride (128 + 16)
static constexpr int B_OFF = BM * RS;            // 18432
static constexpr int STAGE_BYTES = (BM + BN) * RS;      // 36864
static constexpr int SMEM_DYN = STAGES * STAGE_BYTES;   // 110592 -> 2 CTAs/SM

// Fused prep kernel: first WCONV_BLOCKS blocks convert weights (16 elems/thr),
// remaining QUANT_BLOCKS quantize x (32 elems/thr for MLP=8).
static constexpr int WCONV_BLOCKS = (N_TOTAL * K_TOTAL) / (16 * 256);   // 1024
static constexpr int QUANT_BLOCKS = (M_TOTAL * K_TOTAL) / (32 * 256);   // 4096

// ---------------------------------------------------------------------------
// Scratch (36 MB total -> stays L2-resident thanks to .cs streaming elsewhere)
// ---------------------------------------------------------------------------
__device__ uint8_t g_A[(size_t)M_TOTAL * K_TOTAL];   // 32 MB
__device__ uint8_t g_B[(size_t)N_TOTAL * K_TOTAL];   // 4 MB

// ---------------------------------------------------------------------------
// PTX helpers
// ---------------------------------------------------------------------------
DEV uint32_t smem_u32(const void* p) {
    uint32_t a;
    asm("{ .reg .u64 t; cvta.to.shared.u64 t, %1; cvt.u32.u64 %0, t; }" : "=r"(a) : "l"(p));
    return a;
}

#define LDSM_X4(r0, r1, r2, r3, addr) \
    asm volatile("ldmatrix.sync.aligned.m8n8.x4.shared.b16 {%0,%1,%2,%3}, [%4];" \
                 : "=r"(r0), "=r"(r1), "=r"(r2), "=r"(r3) : "r"(addr))

// fp8 e4m3 MMA (validated R5-R14)
#define MMA_E4M3(c, a0, a1, a2, a3, b0, b1) \
    asm volatile("mma.sync.aligned.m16n8k32.row.col.f32.e4m3.e4m3.f32 " \
                 "{%0,%1,%2,%3}, {%4,%5,%6,%7}, {%8,%9}, {%0,%1,%2,%3};" \
                 : "+f"((c)[0]), "+f"((c)[1]), "+f"((c)[2]), "+f"((c)[3]) \
                 : "r"(a0), "r"(a1), "r"(a2), "r"(a3), "r"(b0), "r"(b1))

#define CP_ASYNC_16(dst, src) \
    asm volatile("cp.async.cg.shared.global [%0], [%1], 16;" :: "r"(dst), "l"(src))

// Streaming (evict-first) 16B load: reads that must NOT pollute L2
DEV float4 ldcs4(const float4* p) {
    float4 v;
    asm volatile("ld.global.cs.v4.f32 {%0,%1,%2,%3}, [%4];"
                 : "=f"(v.x), "=f"(v.y), "=f"(v.z), "=f"(v.w) : "l"(p));
    return v;
}
DEV uint4 ldcs4u(const uint4* p) {
    uint4 v;
    asm volatile("ld.global.cs.v4.u32 {%0,%1,%2,%3}, [%4];"
                 : "=r"(v.x), "=r"(v.y), "=r"(v.z), "=r"(v.w) : "l"(p));
    return v;
}
// Streaming 8B store: write-once output, keeps A/B slabs L2-resident
DEV void stcs2(float2* p, float2 v) {
    asm volatile("st.global.cs.v2.f32 [%0], {%1,%2};" :: "l"(p), "f"(v.x), "f"(v.y));
}

DEV bool e4m3_exact(float v) {
    if (!isfinite(v) || fabsf(v) > 448.0f) return false;
    __nv_fp8_e4m3 e(v);
    return (float)e == v;
}

DEV uint4 pack8(const unsigned short* h) {
    uint4 o;
    o.x = (uint32_t)h[0] | ((uint32_t)h[1] << 16);
    o.y = (uint32_t)h[2] | ((uint32_t)h[3] << 16);
    o.z = (uint32_t)h[4] | ((uint32_t)h[5] << 16);
    o.w = (uint32_t)h[6] | ((uint32_t)h[7] << 16);
    return o;
}

DEV uint4 quant16(const float4* v, float r) {
    unsigned short h[8];
#pragma unroll
    for (int j = 0; j < 4; j++) {
        float2 p0 = make_float2(v[j].x * r, v[j].y * r);
        float2 p1 = make_float2(v[j].z * r, v[j].w * r);
        h[2 * j + 0] = (unsigned short)__nv_cvt_float2_to_fp8x2(p0, __NV_SATFINITE, __NV_E4M3);
        h[2 * j + 1] = (unsigned short)__nv_cvt_float2_to_fp8x2(p1, __NV_SATFINITE, __NV_E4M3);
    }
    return pack8(h);
}

// ---------------------------------------------------------------------------
// Kernel 1 (fused prep): blocks [0, WCONV_BLOCKS) -> weight conversion with
// per-block dtype probe; rest -> x quantization at 32 elems/thread (MLP=8).
// All source reads are .cs (evict-first) so g_A/g_B stay L2-resident.
// ---------------------------------------------------------------------------
__global__ void __launch_bounds__(256) fp8lin_prep(const float* __restrict__ x,
                                                   const void* __restrict__ qw,
                                                   const float* __restrict__ in_scale) {
    const int t = threadIdx.x;

    if (blockIdx.x >= WCONV_BLOCKS) {
        // -------- quant path: x -> e4m3, 32 elems/thread, 8 loads in flight ----
        const float r = 1.0f / __ldg(in_scale);
        const size_t i =
            ((size_t)(blockIdx.x - WCONV_BLOCKS) * blockDim.x + t) * 32;
        const float4* src = reinterpret_cast<const float4*>(x + i);

        float4 v[8];
#pragma unroll
        for (int j = 0; j < 8; j++) v[j] = ldcs4(src + j);   // front-load: MLP=8

        uint4* dst = reinterpret_cast<uint4*>(&g_A[i]);
        dst[0] = quant16(v + 0, r);
        dst[1] = quant16(v + 4, r);
        return;
    }

    // ---------------- wconv path with folded dtype probe (R9-R14 validated) ----
    __shared__ int ok32s, okbfs;
    if (t == 0) { ok32s = 1; okbfs = 1; }
    __syncthreads();
    {
        const float* f = (const float*)qw;
        const unsigned short* hb = (const unsigned short*)qw;
        if (!e4m3_exact(f[t])) ok32s = 0;    // benign race: writers all store 0
        bool okbf = e4m3_exact(__bfloat162float(__ushort_as_bfloat16(hb[2 * t]))) &&
                    e4m3_exact(__bfloat162float(__ushort_as_bfloat16(hb[2 * t + 1])));
        if (!okbf) okbfs = 0;
    }
    __syncthreads();
    const int mode = ok32s ? 0 : (okbfs ? 1 : 2);

    const size_t i = ((size_t)blockIdx.x * blockDim.x + t) * 16;
    uint4 o;
    if (mode == 0) {                       // float32 code values (expected)
        const float4* s = reinterpret_cast<const float4*>((const float*)qw + i);
        float4 v[4];
#pragma unroll
        for (int j = 0; j < 4; j++) v[j] = ldcs4(s + j);
        o = quant16(v, 1.0f);              // rn+satfinite is identity on codes
    } else if (mode == 2) {                // raw e4m3 bytes
        o = ldcs4u(reinterpret_cast<const uint4*>((const uint8_t*)qw + i));
    } else {                               // bf16 codes
        const unsigned short* s = (const unsigned short*)qw + i;
        unsigned short h[8];
#pragma unroll
        for (int j = 0; j < 8; j++) {
            float2 p = make_float2(__bfloat162float(__ushort_as_bfloat16(s[2 * j])),
                                   __bfloat162float(__ushort_as_bfloat16(s[2 * j + 1])));
            h[j] = (unsigned short)__nv_cvt_float2_to_fp8x2(p, __NV_SATFINITE, __NV_E4M3);
        }
        o = pack8(h);
    }
    *reinterpret_cast<uint4*>(&g_B[i]) = o;
}

// ---------------------------------------------------------------------------
// Kernel 2: fp8 QMMA GEMM — R7/R10 champion structure, byte-identical to R14
// (timed-run GEMM ~372us with L2-resident A/B; ncu shows 393 under cache flush).
// PROTECTED: do not add register pressure or change mainloop structure.
// ---------------------------------------------------------------------------
__global__ void __launch_bounds__(256, 2) fp8lin_gemm(float* __restrict__ out,
                                                      const float* __restrict__ in_scale,
                                                      const float* __restrict__ w_scale,
                                                      const float* __restrict__ bias) {
    extern __shared__ char dsm[];
    const uint32_t smem0 = smem_u32(dsm);

    const int tid = threadIdx.x;
    const int wid = tid >> 5;
    const int lane = tid & 31;
    const int warp_m = wid >> 2;        // 0..1 -> 64 rows
    const int warp_n = wid & 3;         // 0..3 -> 32 cols

    const int n0 = blockIdx.x * BN;     // N fastest -> A-tile L2 reuse
    const int m0 = blockIdx.y * BM;

    // ---- hoisted loader addressing: 8 src pointers, 8 const dst offsets ----
    const int brow = tid >> 3;          // 0..31
    const int seg = (tid & 7) * 16;     // 0..112
    const uint8_t* sA[4];
    const uint8_t* sB[4];
    uint32_t dA[4], dB[4];
#pragma unroll
    for (int i = 0; i < 4; i++) {
        sA[i] = g_A + (size_t)(m0 + brow + 32 * i) * K_TOTAL + seg;
        sB[i] = g_B + (size_t)(n0 + brow + 32 * i) * K_TOTAL + seg;
        dA[i] = (uint32_t)((brow + 32 * i) * RS + seg);
        dB[i] = (uint32_t)(B_OFF + (brow + 32 * i) * RS + seg);
    }

#define ISSUE_STAGE(stage_base) do { \
        CP_ASYNC_16((stage_base) + dA[0], sA[0]); \
        CP_ASYNC_16((stage_base) + dA[1], sA[1]); \
        CP_ASYNC_16((stage_base) + dA[2], sA[2]); \
        CP_ASYNC_16((stage_base) + dA[3], sA[3]); \
        CP_ASYNC_16((stage_base) + dB[0], sB[0]); \
        CP_ASYNC_16((stage_base) + dB[1], sB[1]); \
        CP_ASYNC_16((stage_base) + dB[2], sB[2]); \
        CP_ASYNC_16((stage_base) + dB[3], sB[3]); \
        sA[0] += BK; sA[1] += BK; sA[2] += BK; sA[3] += BK; \
        sB[0] += BK; sB[1] += BK; sB[2] += BK; sB[3] += BK; \
        asm volatile("cp.async.commit_group;"); \
    } while (0)

    // ---- ldmatrix bases (validated R6/R7) ----
    const int amat = lane >> 3;
    const uint32_t a_base = smem0
        + (uint32_t)((warp_m * 64 + (amat & 1) * 8 + (lane & 7)) * RS + (amat >> 1) * 16);
    const uint32_t b_base = smem0 + (uint32_t)(B_OFF
        + (warp_n * 32 + ((lane >> 4) * 8) + (lane & 7)) * RS + ((lane >> 3) & 1) * 16);

    float acc[4][4][4];
#pragma unroll
    for (int mt = 0; mt < 4; mt++)
#pragma unroll
        for (int nt = 0; nt < 4; nt++)
#pragma unroll
            for (int q = 0; q < 4; q++) acc[mt][nt][q] = 0.0f;

    // Prefill stages 0,1 with chunks 0,1
    ISSUE_STAGE(smem0 + 0 * STAGE_BYTES);
    ISSUE_STAGE(smem0 + 1 * STAGE_BYTES);

#pragma unroll
    for (int c = 0; c < NUM_CHUNKS; c++) {
        if (c < NUM_CHUNKS - 1)
            asm volatile("cp.async.wait_group 1;");
        else
            asm volatile("cp.async.wait_group 0;");
        __syncthreads();

        if (c + 2 < NUM_CHUNKS)
            ISSUE_STAGE(smem0 + (uint32_t)(((c + 2) % STAGES) * STAGE_BYTES));

        const uint32_t soff = (uint32_t)((c % STAGES) * STAGE_BYTES);  // literal
#pragma unroll
        for (int ks = 0; ks < 4; ks++) {
            uint32_t a[4][4], b[4][2];
#pragma unroll
            for (int mt = 0; mt < 4; mt++)
                LDSM_X4(a[mt][0], a[mt][1], a[mt][2], a[mt][3],
                        a_base + soff + (uint32_t)(mt * 16 * RS + ks * 32));
#pragma unroll
            for (int p = 0; p < 2; p++)
                LDSM_X4(b[2 * p][0], b[2 * p][1], b[2 * p + 1][0], b[2 * p + 1][1],
                        b_base + soff + (uint32_t)(p * 16 * RS + ks * 32));
#pragma unroll
            for (int mt = 0; mt < 4; mt++)
#pragma unroll
                for (int nt = 0; nt < 4; nt++)
                    MMA_E4M3(acc[mt][nt], a[mt][0], a[mt][1], a[mt][2], a[mt][3],
                             b[nt][0], b[nt][1]);
        }
    }
#undef ISSUE_STAGE

    // ---------------- Epilogue: dequant scale + bias, streaming stores -------
    const float sc = __ldg(in_scale) * __ldg(w_scale);
    const int gid = lane >> 2;
    const int tig = lane & 3;

    float2 bv[4];
#pragma unroll
    for (int nt = 0; nt < 4; nt++)
        bv[nt] = *reinterpret_cast<const float2*>(bias + n0 + warp_n * 32 + nt * 8 + 2 * tig);

#pragma unroll
    for (int mt = 0; mt < 4; mt++) {
        const int row = m0 + warp_m * 64 + mt * 16 + gid;
#pragma unroll
        for (int nt = 0; nt < 4; nt++) {
            const int col = n0 + warp_n * 32 + nt * 8 + 2 * tig;
            float2 o0, o1;
            o0.x = acc[mt][nt][0] * sc + bv[nt].x;
            o0.y = acc[mt][nt][1] * sc + bv[nt].y;
            o1.x = acc[mt][nt][2] * sc + bv[nt].x;
            o1.y = acc[mt][nt][3] * sc + bv[nt].y;
            stcs2(reinterpret_cast<float2*>(out + (size_t)row * N_TOTAL + col), o0);
            stcs2(reinterpret_cast<float2*>(out + (size_t)(row + 8) * N_TOTAL + col), o1);
        }
    }
}

// ---------------------------------------------------------------------------
// Launch
// ---------------------------------------------------------------------------
extern "C" void kernel_launch(void* const* d_in, const int* in_sizes, int n_in,
                              void* d_out, int out_size) {
    const float* x = nullptr;
    const void* qweight = nullptr;
    const float* bias = nullptr;
    const float* s_first = nullptr;
    const float* s_second = nullptr;
    int x_idx = -1;

    for (int i = 0; i < n_in; i++) {
        long long sz = in_sizes[i];
        if (sz == (long long)M_TOTAL * K_TOTAL) { x = (const float*)d_in[i]; x_idx = i; }
        else if (sz == (long long)N_TOTAL * K_TOTAL) qweight = d_in[i];
        else if (sz == N_TOTAL) bias = (const float*)d_in[i];
        else if (sz == 1) { if (!s_first) s_first = (const float*)d_in[i];
                            else s_second = (const float*)d_in[i]; }
    }
    const float* wscale = (x_idx == 0) ? s_first : s_second;
    const float* iscale = (x_idx == 0) ? s_second : s_first;
    float* out = (float*)d_out;

    // Fused prep: weight conversion + activation quantization in one launch
    fp8lin_prep<<<WCONV_BLOCKS + QUANT_BLOCKS, 256>>>(x, qweight, iscale);

    cudaFuncSetAttribute(fp8lin_gemm, cudaFuncAttributeMaxDynamicSharedMemorySize, SMEM_DYN);
    dim3 grid(N_TOTAL / BN, M_TOTAL / BM);
    fp8lin_gemm<<<grid, 256, SMEM_DYN>>>(out, iscale, wscale, bias);
}

// round 17
// speedup vs baseline: 1.0250x; 1.0250x over previous
#include <cuda_runtime.h>
#include <cuda_bf16.h>
#include <cuda_fp8.h>
#include <cstdint>
#include <math.h>

#define DEV __device__ __forceinline__

// ---------------------------------------------------------------------------
// Problem constants
// ---------------------------------------------------------------------------
static constexpr int M_TOTAL = 16384;   // B*S
static constexpr int N_TOTAL = 2048;    // OUT
static constexpr int K_TOTAL = 2048;    // IN

static constexpr int BM = 128;
static constexpr int BN = 128;
static constexpr int BK = 128;                   // fp8 bytes per K-chunk (full row)
static constexpr int NUM_CHUNKS = K_TOTAL / BK;  // 16
static constexpr int STAGES = 3;
static constexpr int RS = 144;                   // padded row stride (128 + 16)
static constexpr int B_OFF = BM * RS;            // 18432
static constexpr int STAGE_BYTES = (BM + BN) * RS;      // 36864
static constexpr int SMEM_DYN = STAGES * STAGE_BYTES;   // 110592 -> 2 CTAs/SM

// Fused prep: first WCONV_BLOCKS convert weights, rest quantize x.
// Both paths: 16 elems/thread, INTERLEAVED access (warp-coalesced).
static constexpr int WCONV_BLOCKS = (N_TOTAL * K_TOTAL) / (16 * 256);   // 1024
static constexpr int QUANT_BLOCKS = (M_TOTAL * K_TOTAL) / (16 * 256);   // 8192

// ---------------------------------------------------------------------------
// Scratch (36 MB total -> stays L2-resident thanks to .cs streaming elsewhere)
// ---------------------------------------------------------------------------
__device__ uint8_t g_A[(size_t)M_TOTAL * K_TOTAL];   // 32 MB
__device__ uint8_t g_B[(size_t)N_TOTAL * K_TOTAL];   // 4 MB

// ---------------------------------------------------------------------------
// PTX helpers
// ---------------------------------------------------------------------------
DEV uint32_t smem_u32(const void* p) {
    uint32_t a;
    asm("{ .reg .u64 t; cvta.to.shared.u64 t, %1; cvt.u32.u64 %0, t; }" : "=r"(a) : "l"(p));
    return a;
}

#define LDSM_X4(r0, r1, r2, r3, addr) \
    asm volatile("ldmatrix.sync.aligned.m8n8.x4.shared.b16 {%0,%1,%2,%3}, [%4];" \
                 : "=r"(r0), "=r"(r1), "=r"(r2), "=r"(r3) : "r"(addr))

// fp8 e4m3 MMA (validated R5-R15)
#define MMA_E4M3(c, a0, a1, a2, a3, b0, b1) \
    asm volatile("mma.sync.aligned.m16n8k32.row.col.f32.e4m3.e4m3.f32 " \
                 "{%0,%1,%2,%3}, {%4,%5,%6,%7}, {%8,%9}, {%0,%1,%2,%3};" \
                 : "+f"((c)[0]), "+f"((c)[1]), "+f"((c)[2]), "+f"((c)[3]) \
                 : "r"(a0), "r"(a1), "r"(a2), "r"(a3), "r"(b0), "r"(b1))

#define CP_ASYNC_16(dst, src) \
    asm volatile("cp.async.cg.shared.global [%0], [%1], 16;" :: "r"(dst), "l"(src))

// Streaming (evict-first) 16B load: reads that must NOT pollute L2
DEV float4 ldcs4(const float4* p) {
    float4 v;
    asm volatile("ld.global.cs.v4.f32 {%0,%1,%2,%3}, [%4];"
                 : "=f"(v.x), "=f"(v.y), "=f"(v.z), "=f"(v.w) : "l"(p));
    return v;
}
DEV uint4 ldcs4u(const uint4* p) {
    uint4 v;
    asm volatile("ld.global.cs.v4.u32 {%0,%1,%2,%3}, [%4];"
                 : "=r"(v.x), "=r"(v.y), "=r"(v.z), "=r"(v.w) : "l"(p));
    return v;
}
// Streaming 8B store: write-once output, keeps A/B slabs L2-resident
DEV void stcs2(float2* p, float2 v) {
    asm volatile("st.global.cs.v2.f32 [%0], {%1,%2};" :: "l"(p), "f"(v.x), "f"(v.y));
}

DEV bool e4m3_exact(float v) {
    if (!isfinite(v) || fabsf(v) > 448.0f) return false;
    __nv_fp8_e4m3 e(v);
    return (float)e == v;
}

// float4 of values -> 4 packed e4m3 bytes
DEV uint32_t quant4(float4 v, float r) {
    float2 p0 = make_float2(v.x * r, v.y * r);
    float2 p1 = make_float2(v.z * r, v.w * r);
    unsigned short lo = (unsigned short)__nv_cvt_float2_to_fp8x2(p0, __NV_SATFINITE, __NV_E4M3);
    unsigned short hi = (unsigned short)__nv_cvt_float2_to_fp8x2(p1, __NV_SATFINITE, __NV_E4M3);
    return (uint32_t)lo | ((uint32_t)hi << 16);
}

// ---------------------------------------------------------------------------
// Kernel 1 (fused prep): blocks [0, WCONV_BLOCKS) -> weight conversion with
// per-block dtype probe; rest -> x quantization. INTERLEAVED layout: thread t
// handles float4 slots {t, t+256, t+512, t+768} of its block region, so every
// warp load is 512B contiguous and every warp store is 128B contiguous.
// All source reads are .cs (evict-first) so g_A/g_B stay L2-resident.
// ---------------------------------------------------------------------------
__global__ void __launch_bounds__(256) fp8lin_prep(const float* __restrict__ x,
                                                   const void* __restrict__ qw,
                                                   const float* __restrict__ in_scale) {
    const int t = threadIdx.x;

    if (blockIdx.x >= WCONV_BLOCKS) {
        // -------- quant path: x -> e4m3, 16 elems/thread, coalesced ----------
        const float r = 1.0f / __ldg(in_scale);
        const size_t base = (size_t)(blockIdx.x - WCONV_BLOCKS) * 4096;  // floats
        const float4* src = reinterpret_cast<const float4*>(x + base);
        uint32_t* dst = reinterpret_cast<uint32_t*>(&g_A[base]);

        float4 v0 = ldcs4(src + t +   0);      // front-loaded, each warp load
        float4 v1 = ldcs4(src + t + 256);      // = 512B contiguous
        float4 v2 = ldcs4(src + t + 512);
        float4 v3 = ldcs4(src + t + 768);
        dst[t +   0] = quant4(v0, r);          // warp store = 128B contiguous
        dst[t + 256] = quant4(v1, r);
        dst[t + 512] = quant4(v2, r);
        dst[t + 768] = quant4(v3, r);
        return;
    }

    // ---------------- wconv path with folded dtype probe (R9-R15 validated) ----
    __shared__ int ok32s, okbfs;
    if (t == 0) { ok32s = 1; okbfs = 1; }
    __syncthreads();
    {
        const float* f = (const float*)qw;
        const unsigned short* hb = (const unsigned short*)qw;
        if (!e4m3_exact(f[t])) ok32s = 0;    // benign race: writers all store 0
        bool okbf = e4m3_exact(__bfloat162float(__ushort_as_bfloat16(hb[2 * t]))) &&
                    e4m3_exact(__bfloat162float(__ushort_as_bfloat16(hb[2 * t + 1])));
        if (!okbf) okbfs = 0;
    }
    __syncthreads();
    const int mode = ok32s ? 0 : (okbfs ? 1 : 2);

    const size_t base = (size_t)blockIdx.x * 4096;   // elements
    if (mode == 0) {                       // float32 code values (expected)
        const float4* s = reinterpret_cast<const float4*>((const float*)qw + base);
        uint32_t* d = reinterpret_cast<uint32_t*>(&g_B[base]);
        float4 v0 = ldcs4(s + t +   0);
        float4 v1 = ldcs4(s + t + 256);
        float4 v2 = ldcs4(s + t + 512);
        float4 v3 = ldcs4(s + t + 768);
        d[t +   0] = quant4(v0, 1.0f);     // rn+satfinite is identity on codes
        d[t + 256] = quant4(v1, 1.0f);
        d[t + 512] = quant4(v2, 1.0f);
        d[t + 768] = quant4(v3, 1.0f);
    } else if (mode == 2) {                // raw e4m3 bytes: 16B copy per thread
        const uint4* s = reinterpret_cast<const uint4*>((const uint8_t*)qw + base);
        reinterpret_cast<uint4*>(&g_B[base])[t] = ldcs4u(s + t);
    } else {                               // bf16 codes (rare path)
        const unsigned short* s = (const unsigned short*)qw + base;
        uint32_t* d = reinterpret_cast<uint32_t*>(&g_B[base]);
#pragma unroll
        for (int j = 0; j < 4; j++) {
            int slot = t + j * 256;        // 4 bf16 -> 4 e4m3 bytes per slot
            float2 p0 = make_float2(__bfloat162float(__ushort_as_bfloat16(s[4 * slot + 0])),
                                    __bfloat162float(__ushort_as_bfloat16(s[4 * slot + 1])));
            float2 p1 = make_float2(__bfloat162float(__ushort_as_bfloat16(s[4 * slot + 2])),
                                    __bfloat162float(__ushort_as_bfloat16(s[4 * slot + 3])));
            unsigned short lo = (unsigned short)__nv_cvt_float2_to_fp8x2(p0, __NV_SATFINITE, __NV_E4M3);
            unsigned short hi = (unsigned short)__nv_cvt_float2_to_fp8x2(p1, __NV_SATFINITE, __NV_E4M3);
            d[slot] = (uint32_t)lo | ((uint32_t)hi << 16);
        }
    }
}

// ---------------------------------------------------------------------------
// Kernel 2: fp8 QMMA GEMM — R7/R14 champion structure, byte-identical
// (timed-run GEMM ~372us with L2-resident A/B; ncu shows 393 under cache flush).
// PROTECTED: do not add register pressure or change mainloop structure.
// ---------------------------------------------------------------------------
__global__ void __launch_bounds__(256, 2) fp8lin_gemm(float* __restrict__ out,
                                                      const float* __restrict__ in_scale,
                                                      const float* __restrict__ w_scale,
                                                      const float* __restrict__ bias) {
    extern __shared__ char dsm[];
    const uint32_t smem0 = smem_u32(dsm);

    const int tid = threadIdx.x;
    const int wid = tid >> 5;
    const int lane = tid & 31;
    const int warp_m = wid >> 2;        // 0..1 -> 64 rows
    const int warp_n = wid & 3;         // 0..3 -> 32 cols

    const int n0 = blockIdx.x * BN;     // N fastest -> A-tile L2 reuse
    const int m0 = blockIdx.y * BM;

    // ---- hoisted loader addressing: 8 src pointers, 8 const dst offsets ----
    const int brow = tid >> 3;          // 0..31
    const int seg = (tid & 7) * 16;     // 0..112
    const uint8_t* sA[4];
    const uint8_t* sB[4];
    uint32_t dA[4], dB[4];
#pragma unroll
    for (int i = 0; i < 4; i++) {
        sA[i] = g_A + (size_t)(m0 + brow + 32 * i) * K_TOTAL + seg;
        sB[i] = g_B + (size_t)(n0 + brow + 32 * i) * K_TOTAL + seg;
        dA[i] = (uint32_t)((brow + 32 * i) * RS + seg);
        dB[i] = (uint32_t)(B_OFF + (brow + 32 * i) * RS + seg);
    }

#define ISSUE_STAGE(stage_base) do { \
        CP_ASYNC_16((stage_base) + dA[0], sA[0]); \
        CP_ASYNC_16((stage_base) + dA[1], sA[1]); \
        CP_ASYNC_16((stage_base) + dA[2], sA[2]); \
        CP_ASYNC_16((stage_base) + dA[3], sA[3]); \
        CP_ASYNC_16((stage_base) + dB[0], sB[0]); \
        CP_ASYNC_16((stage_base) + dB[1], sB[1]); \
        CP_ASYNC_16((stage_base) + dB[2], sB[2]); \
        CP_ASYNC_16((stage_base) + dB[3], sB[3]); \
        sA[0] += BK; sA[1] += BK; sA[2] += BK; sA[3] += BK; \
        sB[0] += BK; sB[1] += BK; sB[2] += BK; sB[3] += BK; \
        asm volatile("cp.async.commit_group;"); \
    } while (0)

    // ---- ldmatrix bases (validated R6/R7) ----
    const int amat = lane >> 3;
    const uint32_t a_base = smem0
        + (uint32_t)((warp_m * 64 + (amat & 1) * 8 + (lane & 7)) * RS + (amat >> 1) * 16);
    const uint32_t b_base = smem0 + (uint32_t)(B_OFF
        + (warp_n * 32 + ((lane >> 4) * 8) + (lane & 7)) * RS + ((lane >> 3) & 1) * 16);

    float acc[4][4][4];
#pragma unroll
    for (int mt = 0; mt < 4; mt++)
#pragma unroll
        for (int nt = 0; nt < 4; nt++)
#pragma unroll
            for (int q = 0; q < 4; q++) acc[mt][nt][q] = 0.0f;

    // Prefill stages 0,1 with chunks 0,1
    ISSUE_STAGE(smem0 + 0 * STAGE_BYTES);
    ISSUE_STAGE(smem0 + 1 * STAGE_BYTES);

#pragma unroll
    for (int c = 0; c < NUM_CHUNKS; c++) {
        if (c < NUM_CHUNKS - 1)
            asm volatile("cp.async.wait_group 1;");
        else
            asm volatile("cp.async.wait_group 0;");
        __syncthreads();

        if (c + 2 < NUM_CHUNKS)
            ISSUE_STAGE(smem0 + (uint32_t)(((c + 2) % STAGES) * STAGE_BYTES));

        const uint32_t soff = (uint32_t)((c % STAGES) * STAGE_BYTES);  // literal
#pragma unroll
        for (int ks = 0; ks < 4; ks++) {
            uint32_t a[4][4], b[4][2];
#pragma unroll
            for (int mt = 0; mt < 4; mt++)
                LDSM_X4(a[mt][0], a[mt][1], a[mt][2], a[mt][3],
                        a_base + soff + (uint32_t)(mt * 16 * RS + ks * 32));
#pragma unroll
            for (int p = 0; p < 2; p++)
                LDSM_X4(b[2 * p][0], b[2 * p][1], b[2 * p + 1][0], b[2 * p + 1][1],
                        b_base + soff + (uint32_t)(p * 16 * RS + ks * 32));
#pragma unroll
            for (int mt = 0; mt < 4; mt++)
#pragma unroll
                for (int nt = 0; nt < 4; nt++)
                    MMA_E4M3(acc[mt][nt], a[mt][0], a[mt][1], a[mt][2], a[mt][3],
                             b[nt][0], b[nt][1]);
        }
    }
#undef ISSUE_STAGE

    // ---------------- Epilogue: dequant scale + bias, streaming stores -------
    const float sc = __ldg(in_scale) * __ldg(w_scale);
    const int gid = lane >> 2;
    const int tig = lane & 3;

    float2 bv[4];
#pragma unroll
    for (int nt = 0; nt < 4; nt++)
        bv[nt] = *reinterpret_cast<const float2*>(bias + n0 + warp_n * 32 + nt * 8 + 2 * tig);

#pragma unroll
    for (int mt = 0; mt < 4; mt++) {
        const int row = m0 + warp_m * 64 + mt * 16 + gid;
#pragma unroll
        for (int nt = 0; nt < 4; nt++) {
            const int col = n0 + warp_n * 32 + nt * 8 + 2 * tig;
            float2 o0, o1;
            o0.x = acc[mt][nt][0] * sc + bv[nt].x;
            o0.y = acc[mt][nt][1] * sc + bv[nt].y;
            o1.x = acc[mt][nt][2] * sc + bv[nt].x;
            o1.y = acc[mt][nt][3] * sc + bv[nt].y;
            stcs2(reinterpret_cast<float2*>(out + (size_t)row * N_TOTAL + col), o0);
            stcs2(reinterpret_cast<float2*>(out + (size_t)(row + 8) * N_TOTAL + col), o1);
        }
    }
}

// ---------------------------------------------------------------------------
// Launch
// ---------------------------------------------------------------------------
extern "C" void kernel_launch(void* const* d_in, const int* in_sizes, int n_in,
                              void* d_out, int out_size) {
    const float* x = nullptr;
    const void* qweight = nullptr;
    const float* bias = nullptr;
    const float* s_first = nullptr;
    const float* s_second = nullptr;
    int x_idx = -1;

    for (int i = 0; i < n_in; i++) {
        long long sz = in_sizes[i];
        if (sz == (long long)M_TOTAL * K_TOTAL) { x = (const float*)d_in[i]; x_idx = i; }
        else if (sz == (long long)N_TOTAL * K_TOTAL) qweight = d_in[i];
        else if (sz == N_TOTAL) bias = (const float*)d_in[i];
        else if (sz == 1) { if (!s_first) s_first = (const float*)d_in[i];
                            else s_second = (const float*)d_in[i]; }
    }
    const float* wscale = (x_idx == 0) ? s_first : s_second;
    const float* iscale = (x_idx == 0) ? s_second : s_first;
    float* out = (float*)d_out;

    // Fused prep: weight conversion + activation quantization in one launch
    fp8lin_prep<<<WCONV_BLOCKS + QUANT_BLOCKS, 256>>>(x, qweight, iscale);

    cudaFuncSetAttribute(fp8lin_gemm, cudaFuncAttributeMaxDynamicSharedMemorySize, SMEM_DYN);
    dim3 grid(N_TOTAL / BN, M_TOTAL / BM);
    fp8lin_gemm<<<grid, 256, SMEM_DYN>>>(out, iscale, wscale, bias);
}